// round 7
// baseline (speedup 1.0000x reference)
#include <cuda_runtime.h>

// ---------------------------------------------------------------------------
// PCritical step, B=32, N=4096 — fused single pass over W, sparse-spike GEMMs,
// deterministic in-kernel partial reduction.
// Outputs concatenated float32 in reference return order:
//   S (B,N) | mem_pot_n (B,N) | W_new (N,N) | mem_cur_n (B,N) |
//   mem_pot_p_n (B,N) | mem_cur_p_n (B,N) | refrac_new (B,N)
// ---------------------------------------------------------------------------

#define Bsz 32
#define Nsz 4096
#define BN  (Bsz * Nsz)        // 131072
#define NN  (Nsz * Nsz)        // 16777216

#define C_ALPHA 0.025f
#define C_BETA  0.00025f
#define C_TNOW  10.0f
#define C_INV_TAU_V 0.9801986733067553f
#define C_INV_TAU_I 0.36787944117144233f

#define OUT_S    ((long long)0)
#define OUT_POT  ((long long)BN)
#define OUT_W    ((long long)(2LL * BN))
#define OUT_CUR  ((long long)(2LL * BN + NN))
#define OUT_POTP ((long long)(3LL * BN + NN))
#define OUT_CURP ((long long)(4LL * BN + NN))
#define OUT_REFR ((long long)(5LL * BN + NN))

#define ICHUNKS 16             // 4096 / 256  (grid.y)
#define JCHUNKS 32             // 4096 / 128  (grid.x)
#define PITCH   129            // 129 ≡ 1 (mod 32): rows AND cols conflict-free

// scratch (no dynamic allocation allowed)
__device__ __align__(16) unsigned g_masks[Nsz];          // bit b <=> S[b,n]==1
__device__ __align__(16) float    g_e[Nsz];
__device__ __align__(16) float    g_ie[Nsz];
__device__ __align__(16) float    g_A[Nsz];              // sp ? ALPHA*e  : 0
__device__ __align__(16) float    g_Ai[Nsz];             // sp ? ALPHA*ie : 0
__device__ __align__(16) float    g_accP[ICHUNKS * BN];  // partials S@W_new
__device__ __align__(16) float    g_accTP[JCHUNKS * BN]; // partials S@W_new^T
__device__ __align__(16) float    g_accF[BN];            // reduced S@W_new
__device__ __align__(16) float    g_accTF[BN];           // reduced S@W_new^T
__device__ int g_cntP[JCHUNKS];                          // arrival counters
__device__ int g_cntT[ICHUNKS];

// ---------------------------------------------------------------------------
// K1: per-neuron batch reductions + exp precompute; also resets counters.
// 4-way batch split per neuron (4 threads/neuron, 8 batch rows each),
// merged with 2 shfl_xor steps — 4x MLP for this latency-bound scan.
// ---------------------------------------------------------------------------
__global__ void __launch_bounds__(128) k_prologue(
    const float* __restrict__ mem_pot,
    const float* __restrict__ mem_pot_paired,
    const float* __restrict__ st)
{
    int gid = blockIdx.x * 128 + threadIdx.x;   // 4*Nsz = 16384 threads
    if (blockIdx.x == 0 && threadIdx.x < JCHUNKS + ICHUNKS) {
        if (threadIdx.x < JCHUNKS) g_cntP[threadIdx.x] = 0;
        else                       g_cntT[threadIdx.x - JCHUNKS] = 0;
    }
    int n = gid >> 2;
    int q = gid & 3;
    int b0 = q * 8;

    unsigned mp_ = 0u;
    bool anyp = false;
#pragma unroll
    for (int k = 0; k < 8; ++k) {
        int b = b0 + k;
        float mp = mem_pot[b * Nsz + n];
        if (mp > 1.0f) mp_ |= (1u << b);
        float mpp = mem_pot_paired[b * Nsz + n];
        if (((mpp - 1.0f) - C_ALPHA) > 0.0f) anyp = true;
    }
    mp_ |= __shfl_xor_sync(0xffffffffu, mp_, 1);
    anyp = anyp | (bool)__shfl_xor_sync(0xffffffffu, (int)anyp, 1);
    mp_ |= __shfl_xor_sync(0xffffffffu, mp_, 2);
    anyp = anyp | (bool)__shfl_xor_sync(0xffffffffu, (int)anyp, 2);

    if (q == 0) {
        unsigned m = mp_;
        float stn = st[n];
        float maxst = (m == 0xffffffffu) ? C_TNOW
                    : (m ? fmaxf(C_TNOW, stn) : stn);
        float e  = expf(maxst * (1.0f / 50.0f));
        float ie = expf(-maxst * (1.0f / 50.0f));
        g_masks[n] = m;
        g_e[n]  = e;
        g_ie[n] = ie;
        g_A[n]  = anyp ? C_ALPHA * e  : 0.0f;
        g_Ai[n] = anyp ? C_ALPHA * ie : 0.0f;
    }
}

__device__ __forceinline__ float upd1(float w, float A, float Ai, float e, float ie)
{
    float sub = fmaxf(A * ie, Ai * e);        // 0 when row not paired-spiking
    float u = (w + C_BETA) - sub;
    u = fminf(fmaxf(u, 0.0f), 1.0f);
    return (w > 0.0f) ? u : w;                // sign_mask = W_rec > 0
}

// ---------------------------------------------------------------------------
// K2 (fused): W update + both binary-S GEMMs (R4 proven core) + deterministic
// last-arrival chunk reduction in the tail.
// 512 threads, 2 blocks/SM. Tile 256 i x 128 j as 2 subtiles of 128x128.
// ---------------------------------------------------------------------------
__global__ void __launch_bounds__(512, 2) k_fused(
    const float* __restrict__ W, float* __restrict__ Wout)
{
    extern __shared__ float sm[];
    float*    c   = sm;                                  // [128][129]
    unsigned* rbi = (unsigned*)(sm + 128 * PITCH);       // [32][4] rows per b
    unsigned* rbj = rbi + 128;                           // [32][4] cols per b
    int*      sflag = (int*)(rbj + 128);                 // [2] last-block flags

    const int jc   = blockIdx.x;       // 0..31
    const int ic   = blockIdx.y;       // 0..15
    const int tid  = threadIdx.x;
    const int warp = tid >> 5;         // 0..15
    const int lane = tid & 31;
    const int jg0  = jc * 128;

    // per-column exp factors (block-constant)
    float e0  = g_e[jg0 + lane];       float ie0 = g_ie[jg0 + lane];
    float e1  = g_e[jg0 + lane + 32];  float ie1 = g_ie[jg0 + lane + 32];
    float e2  = g_e[jg0 + lane + 64];  float ie2 = g_ie[jg0 + lane + 64];
    float e3  = g_e[jg0 + lane + 96];  float ie3 = g_ie[jg0 + lane + 96];

    // transposed column masks (block-constant)
    if (warp < 4) {
        unsigned mw = g_masks[jg0 + warp * 32 + lane];
#pragma unroll
        for (int b = 0; b < 32; ++b) {
            unsigned w = __ballot_sync(0xffffffffu, (mw >> b) & 1u);
            if (lane == b) rbj[b * 4 + warp] = w;
        }
    }

    // Phase-B accumulators persist across both subtiles (same ic chunk)
    float aJ0 = 0, aJ1 = 0, aJ2 = 0, aJ3 = 0;   // b = warp
    float bJ0 = 0, bJ1 = 0, bJ2 = 0, bJ3 = 0;   // b = warp + 16

    const int lp = lane * PITCH;

#pragma unroll
    for (int s = 0; s < 2; ++s) {
        const int ig0 = ic * 256 + s * 128;
        if (s) __syncthreads();        // previous subtile fully consumed

        // ---- Phase A: update 8 contiguous rows per warp ----
#pragma unroll
        for (int r = 0; r < 8; ++r) {
            int il = warp * 8 + r;
            int ig = ig0 + il;
            float A  = g_A[ig];
            float Ai = g_Ai[ig];
            const float* wr = W    + (size_t)ig * Nsz + jg0;
            float*       wo = Wout + (size_t)ig * Nsz + jg0;
            float w0 = wr[lane];
            float w1 = wr[lane + 32];
            float w2 = wr[lane + 64];
            float w3 = wr[lane + 96];
            float u0 = upd1(w0, A, Ai, e0, ie0);
            float u1 = upd1(w1, A, Ai, e1, ie1);
            float u2 = upd1(w2, A, Ai, e2, ie2);
            float u3 = upd1(w3, A, Ai, e3, ie3);
            wo[lane]      = u0;
            wo[lane + 32] = u1;
            wo[lane + 64] = u2;
            wo[lane + 96] = u3;
            float* cr = c + il * PITCH;
            cr[lane]      = u0;
            cr[lane + 32] = u1;
            cr[lane + 64] = u2;
            cr[lane + 96] = u3;
        }
        // transposed row masks for this subtile (warps 4..7)
        if (warp >= 4 && warp < 8) {
            int q = warp - 4;
            unsigned mw = g_masks[ig0 + q * 32 + lane];
#pragma unroll
            for (int b = 0; b < 32; ++b) {
                unsigned w = __ballot_sync(0xffffffffu, (mw >> b) & 1u);
                if (lane == b) rbi[b * 4 + q] = w;
            }
        }
        __syncthreads();

        // ---- Phase B: acc[b][j] over active rows (uniform ffs loop) ----
#pragma unroll
        for (int q = 0; q < 4; ++q) {
            unsigned m = rbi[warp * 4 + q];
            while (m) {
                int r = q * 32 + __ffs(m) - 1; m &= m - 1;
                const float* cr = c + r * PITCH;
                aJ0 += cr[lane];
                aJ1 += cr[lane + 32];
                aJ2 += cr[lane + 64];
                aJ3 += cr[lane + 96];
            }
        }
#pragma unroll
        for (int q = 0; q < 4; ++q) {
            unsigned m = rbi[(warp + 16) * 4 + q];
            while (m) {
                int r = q * 32 + __ffs(m) - 1; m &= m - 1;
                const float* cr = c + r * PITCH;
                bJ0 += cr[lane];
                bJ1 += cr[lane + 32];
                bJ2 += cr[lane + 64];
                bJ3 += cr[lane + 96];
            }
        }

        // ---- Phase C: accT[b][i] over active cols ----
        {
            float aI0 = 0, aI1 = 0, aI2 = 0, aI3 = 0;
            float bI0 = 0, bI1 = 0, bI2 = 0, bI3 = 0;
#pragma unroll
            for (int q = 0; q < 4; ++q) {
                unsigned m = rbj[warp * 4 + q];
                while (m) {
                    int j = q * 32 + __ffs(m) - 1; m &= m - 1;
                    const float* cc = c + j + lp;
                    aI0 += cc[0];
                    aI1 += cc[32 * PITCH];
                    aI2 += cc[64 * PITCH];
                    aI3 += cc[96 * PITCH];
                }
            }
#pragma unroll
            for (int q = 0; q < 4; ++q) {
                unsigned m = rbj[(warp + 16) * 4 + q];
                while (m) {
                    int j = q * 32 + __ffs(m) - 1; m &= m - 1;
                    const float* cc = c + j + lp;
                    bI0 += cc[0];
                    bI1 += cc[32 * PITCH];
                    bI2 += cc[64 * PITCH];
                    bI3 += cc[96 * PITCH];
                }
            }
            size_t oa = ((size_t)jc * Bsz + warp) * Nsz + ig0 + lane;
            g_accTP[oa]      = aI0;
            g_accTP[oa + 32] = aI1;
            g_accTP[oa + 64] = aI2;
            g_accTP[oa + 96] = aI3;
            size_t ob = ((size_t)jc * Bsz + warp + 16) * Nsz + ig0 + lane;
            g_accTP[ob]      = bI0;
            g_accTP[ob + 32] = bI1;
            g_accTP[ob + 64] = bI2;
            g_accTP[ob + 96] = bI3;
        }
    }

    // Phase-B partial writes (one per ic chunk)
    {
        size_t oa = ((size_t)ic * Bsz + warp) * Nsz + jg0 + lane;
        g_accP[oa]      = aJ0;
        g_accP[oa + 32] = aJ1;
        g_accP[oa + 64] = aJ2;
        g_accP[oa + 96] = aJ3;
        size_t ob = ((size_t)ic * Bsz + warp + 16) * Nsz + jg0 + lane;
        g_accP[ob]      = bJ0;
        g_accP[ob + 32] = bJ1;
        g_accP[ob + 64] = bJ2;
        g_accP[ob + 96] = bJ3;
    }

    // ---- Tail: deterministic last-arrival chunk reductions ----
    __syncthreads();                   // all partial STGs issued
    if (tid == 0) {
        __threadfence();               // make partials visible
        sflag[0] = (atomicAdd(&g_cntP[jc], 1) == ICHUNKS - 1);
        sflag[1] = (atomicAdd(&g_cntT[ic], 1) == JCHUNKS - 1);
    }
    __syncthreads();

    if (sflag[0]) {                    // last for this jc: reduce acc over ic
        __threadfence();
#pragma unroll
        for (int k = 0; k < 8; ++k) {  // 4096 (b,j) pairs / 512 threads
            int p  = tid + 512 * k;
            int b  = p >> 7;
            int jl = p & 127;
            size_t base = (size_t)b * Nsz + jg0 + jl;
            float s0 = 0.0f;
#pragma unroll
            for (int cc = 0; cc < ICHUNKS; ++cc)
                s0 += g_accP[(size_t)cc * BN + base];
            g_accF[base] = s0;
        }
    }
    if (sflag[1]) {                    // last for this ic: reduce accT over jc
        __threadfence();
#pragma unroll
        for (int k = 0; k < 16; ++k) { // 8192 (b,i) pairs / 512 threads
            int p  = tid + 512 * k;
            int b  = p >> 8;
            int il = p & 255;
            size_t base = (size_t)b * Nsz + ic * 256 + il;
            float s0 = 0.0f;
#pragma unroll
            for (int cc = 0; cc < JCHUNKS; ++cc)
                s0 += g_accTP[(size_t)cc * BN + base];
            g_accTF[base] = s0;
        }
    }
}

// ---------------------------------------------------------------------------
// K3: epilogue — integrate, leak, reset, refractory (reads reduced accs)
// ---------------------------------------------------------------------------
__global__ void __launch_bounds__(256) k_epilogue(
    const float* __restrict__ inp,
    const float* __restrict__ mem_pot,
    const float* __restrict__ mem_cur,
    const float* __restrict__ mem_pot_paired,
    const float* __restrict__ mem_cur_paired,
    const int*   __restrict__ refrac,
    float* __restrict__ out)
{
    int t = blockIdx.x * 256 + threadIdx.x;   // BN threads
    int b = t >> 12;
    int n = t & (Nsz - 1);

    float acc  = g_accF[t];
    float accT = g_accTF[t];

    int r  = refrac[t];
    int rd = (r > 0) ? (r - 1) : r;
    bool active = (rd == 0);

    unsigned m = g_masks[n];
    bool s  = ((m >> b) & 1u) != 0u;
    float mppv = mem_pot_paired[t];
    bool sp = ((mppv - 1.0f) - C_ALPHA) > 0.0f;

    float mp   = mem_pot[t];
    float mc   = mem_cur[t];
    float mcpv = mem_cur_paired[t];

    float mcn  = active ? (inp[t] + acc) + mc : mc;
    float mcpn = active ? accT + mcpv : mcpv;
    float mpn  = active ? mcn + mp : mp;
    float mppn = active ? mcpn + mppv : mppv;

    mpn  *= C_INV_TAU_V;
    mcn  *= C_INV_TAU_I;
    mppn *= C_INV_TAU_V;
    mcpn *= C_INV_TAU_I;

    if (s)  mpn  = 0.0f;
    if (sp) mppn = 0.0f;
    float rn = s ? 2.0f : (float)rd;

    out[OUT_S    + t] = s ? 1.0f : 0.0f;
    out[OUT_POT  + t] = mpn;
    out[OUT_CUR  + t] = mcn;
    out[OUT_POTP + t] = mppn;
    out[OUT_CURP + t] = mcpn;
    out[OUT_REFR + t] = rn;
}

// ---------------------------------------------------------------------------
extern "C" void kernel_launch(void* const* d_in, const int* in_sizes, int n_in,
                              void* d_out, int out_size)
{
    const float* inp      = (const float*)d_in[0];
    const float* W_rec    = (const float*)d_in[1];
    const float* mem_pot  = (const float*)d_in[2];
    const float* mem_cur  = (const float*)d_in[3];
    const float* mpp      = (const float*)d_in[4];
    const float* mcp      = (const float*)d_in[5];
    const float* st       = (const float*)d_in[6];
    const int*   refrac   = (const int*)d_in[7];
    float* out = (float*)d_out;
    float* Wout = out + OUT_W;

    const int smem_bytes = (128 * PITCH + 256 + 8) * 4;   // ~67 KB -> 2 blocks/SM
    cudaFuncSetAttribute(k_fused, cudaFuncAttributeMaxDynamicSharedMemorySize,
                         smem_bytes);

    k_prologue<<<4 * Nsz / 128, 128>>>(mem_pot, mpp, st);
    k_fused<<<dim3(JCHUNKS, ICHUNKS), 512, smem_bytes>>>(W_rec, Wout);
    k_epilogue<<<BN / 256, 256>>>(inp, mem_pot, mem_cur, mpp, mcp, refrac, out);
}